// round 11
// baseline (speedup 1.0000x reference)
#include <cuda_runtime.h>
#include <cuda_bf16.h>

// out[p,o] = sum_d x[p,d]*(W[d,o] + eps[p,d,o]) + bias[o] + bias_eps[p,o]
// P=1024, D=512, O=512, fp32.
//
// TERMINAL FORM — at the HBM roofline. Mandatory DRAM traffic 1081 MB
// (eps 1073.7 MB read-once + x + W + bias_eps + out write) at the measured
// ~7.0 TB/s streaming plateau (87-88% of spec) -> ~154us kernel floor.
// Single kernel, 1280 CTAs x 128 threads, ONE wave (enforced by
// __launch_bounds__(128, 9): 9 CTAs/SM min residency -> regs capped <= 56):
//   - CTAs [0, 256): tiled GEMM, writes out = x@W + bias + bias_eps directly.
//     First in grid -> scheduled/retired earliest; spin-gate deadlock-free.
//   - CTAs [256, 1280): stream eps for row p (~150us, HBM-bound), gate on the
//     GEMM flag (set ~130us earlier), then out[p,:] += epsdot (L2-hot).
// eps / bias_eps read evict-first (.cs); out stored .cs. Gate spins on a
// volatile load (no L2 atomic RMW storm). Counters self-reset per launch ->
// graph-replay deterministic.
//
// Falsified alternatives (do not revisit): 256-thr d-split (2 waves, -10us),
// g_xw scratch (+2MB write), separate combine kernel (+5us), folding W into
// stream CTAs (LTS cap), wider MLP via deeper unroll (reg-residency budget).

#define PP 1024
#define DD 512
#define OO 512
#define GEMM_CTAS 256          // (1024/32 rows) * (512/64 cols)

__device__ int g_done = 0;           // GEMM CTAs completed
__device__ int g_stream_done = 0;    // stream CTAs past the gate

__global__ __launch_bounds__(128, 9)
void nes_fused(const float* __restrict__ x,
               const float* __restrict__ w,
               const float* __restrict__ bias,
               const float* __restrict__ eps,
               const float* __restrict__ bias_eps,
               float* __restrict__ out) {
    const int bid = blockIdx.x;
    const int tid = threadIdx.x;   // 0..127

    if (bid >= GEMM_CTAS) {
        // ------------------ eps stream CTA: one row p ------------------
        __shared__ float xs[DD];
        const int p = bid - GEMM_CTAS;

        ((float4*)xs)[tid] = ((const float4*)(x + (size_t)p * DD))[tid];
        __syncthreads();

        const float4* e = (const float4*)(eps + (size_t)p * DD * OO) + tid;

        float4 acc = make_float4(0.f, 0.f, 0.f, 0.f);
        #pragma unroll 8
        for (int d = 0; d < DD; d++) {
            float4 v = __ldcs(&e[d * (OO / 4)]);   // evict-first: pure stream
            float xv = xs[d];
            acc.x = fmaf(xv, v.x, acc.x);
            acc.y = fmaf(xv, v.y, acc.y);
            acc.z = fmaf(xv, v.z, acc.z);
            acc.w = fmaf(xv, v.w, acc.w);
        }

        // ---- gate: wait for all GEMM CTAs (in practice already done) ----
        if (tid == 0) {
            volatile int* done = &g_done;
            while (*done < GEMM_CTAS) { }
        }
        __syncthreads();
        __threadfence();   // acquire: order the out-row read after the flag

        // out[p,:] currently holds x@W + bias + bias_eps (written by GEMM CTAs).
        float4* orow = (float4*)(out + (size_t)p * OO);
        float4 base = __ldcg(&orow[tid]);   // L2-hot (written ~130us earlier)

        float4 o;
        o.x = acc.x + base.x;
        o.y = acc.y + base.y;
        o.z = acc.z + base.z;
        o.w = acc.w + base.w;
        __stcs(&orow[tid], o);   // write-once stream

        // ---- self-reset for next graph replay ----
        if (tid == 0) {
            int old = atomicAdd(&g_stream_done, 1);
            if (old == PP - 1) {
                // All stream CTAs have passed the gate; safe to reset.
                atomicExch(&g_stream_done, 0);
                atomicExch(&g_done, 0);
            }
        }
    } else {
        // ---- GEMM CTA: 32x64 tile, writes out = x@W + bias + bias_eps ----
        __shared__ float As[16][32];   // [k][m]
        __shared__ float Bs[16][64];   // [k][n]

        const int g  = bid;
        const int bm = (g >> 3) * 32;
        const int bn = (g & 7) * 64;
        const int tx = tid & 15;
        const int ty = tid >> 4;

        float acc[4][4];
        #pragma unroll
        for (int i = 0; i < 4; i++)
            #pragma unroll
            for (int j = 0; j < 4; j++) acc[i][j] = 0.0f;

        for (int k0 = 0; k0 < DD; k0 += 16) {
            {
                const int r  = tid >> 2;           // 0..31
                const int c4 = (tid & 3) * 4;      // 0,4,8,12
                float4 a = *(const float4*)&x[(size_t)(bm + r) * DD + k0 + c4];
                As[c4 + 0][r] = a.x;
                As[c4 + 1][r] = a.y;
                As[c4 + 2][r] = a.z;
                As[c4 + 3][r] = a.w;
            }
            {
                const int r  = tid >> 4;           // 0..7
                const int c4 = (tid & 15) * 4;
                *(float4*)&Bs[r][c4]     = *(const float4*)&w[(size_t)(k0 + r) * OO + bn + c4];
                *(float4*)&Bs[r + 8][c4] = *(const float4*)&w[(size_t)(k0 + r + 8) * OO + bn + c4];
            }
            __syncthreads();

            #pragma unroll
            for (int k = 0; k < 16; k++) {
                float4 a = *(const float4*)&As[k][ty * 4];
                float4 b = *(const float4*)&Bs[k][tx * 4];
                float av[4] = {a.x, a.y, a.z, a.w};
                float bv[4] = {b.x, b.y, b.z, b.w};
                #pragma unroll
                for (int i = 0; i < 4; i++)
                    #pragma unroll
                    for (int j = 0; j < 4; j++)
                        acc[i][j] = fmaf(av[i], bv[j], acc[i][j]);
            }
            __syncthreads();
        }

        // Epilogue: out = acc + bias + bias_eps (stream CTAs add epsdot later).
        #pragma unroll
        for (int i = 0; i < 4; i++) {
            const int row = bm + ty * 4 + i;
            #pragma unroll
            for (int j = 0; j < 4; j++) {
                const int col = bn + tx * 4 + j;
                out[(size_t)row * OO + col] =
                    acc[i][j] + bias[col]
                    + __ldcs(&bias_eps[(size_t)row * OO + col]);  // read-once
            }
        }

        __threadfence();   // release: publish the out rows before the flag
        __syncthreads();
        if (tid == 0) atomicAdd(&g_done, 1);
    }
}

extern "C" void kernel_launch(void* const* d_in, const int* in_sizes, int n_in,
                              void* d_out, int out_size) {
    const float* x        = (const float*)d_in[0];
    const float* w        = (const float*)d_in[1];
    const float* bias     = (const float*)d_in[2];
    const float* eps      = (const float*)d_in[3];
    const float* bias_eps = (const float*)d_in[4];
    float*       out      = (float*)d_out;

    (void)in_sizes; (void)n_in; (void)out_size;

    nes_fused<<<PP + GEMM_CTAS, 128>>>(x, w, bias, eps, bias_eps, out);
}

// round 12
// speedup vs baseline: 1.0117x; 1.0117x over previous
#include <cuda_runtime.h>
#include <cuda_bf16.h>

// out[p,o] = sum_d x[p,d]*(W[d,o] + eps[p,d,o]) + bias[o] + bias_eps[p,o]
// P=1024, D=512, O=512, fp32.
//
// TERMINAL FORM (verified best: 152.2us, DRAM 88.6%, regs 48) — at the HBM
// roofline. Mandatory DRAM traffic 1081 MB (eps 1073.7 MB read-once + x + W +
// bias_eps + out write) at the measured ~7.0 TB/s streaming plateau -> ~154us.
// Single kernel, 1280 CTAs x 128 threads, one wave:
//   - CTAs [0, 256): tiled GEMM, writes out = x@W + bias + bias_eps directly.
//     First in grid -> scheduled/retired earliest; spin-gate deadlock-free.
//   - CTAs [256, 1280): stream eps for row p (~150us, HBM-bound), gate on the
//     GEMM flag (set ~130us earlier), then out[p,:] += epsdot (L2-hot).
// eps / bias_eps read evict-first (.cs); out stored .cs. Gate spins on a
// volatile load. Counters self-reset per launch -> graph-replay deterministic.
//
// Falsified (do not revisit): 256-thr d-split (2 waves, -10us); g_xw scratch
// (+2MB); separate combine kernel (+5us); W folded into stream CTAs (LTS cap);
// __launch_bounds__(128,9) pin (ptxas burns the reg budget 48->55 and
// reschedules the stream loop worse: -6us).

#define PP 1024
#define DD 512
#define OO 512
#define GEMM_CTAS 256          // (1024/32 rows) * (512/64 cols)

__device__ int g_done = 0;           // GEMM CTAs completed
__device__ int g_stream_done = 0;    // stream CTAs past the gate

__global__ __launch_bounds__(128)
void nes_fused(const float* __restrict__ x,
               const float* __restrict__ w,
               const float* __restrict__ bias,
               const float* __restrict__ eps,
               const float* __restrict__ bias_eps,
               float* __restrict__ out) {
    const int bid = blockIdx.x;
    const int tid = threadIdx.x;   // 0..127

    if (bid >= GEMM_CTAS) {
        // ------------------ eps stream CTA: one row p ------------------
        __shared__ float xs[DD];
        const int p = bid - GEMM_CTAS;

        ((float4*)xs)[tid] = ((const float4*)(x + (size_t)p * DD))[tid];
        __syncthreads();

        const float4* e = (const float4*)(eps + (size_t)p * DD * OO) + tid;

        float4 acc = make_float4(0.f, 0.f, 0.f, 0.f);
        #pragma unroll 8
        for (int d = 0; d < DD; d++) {
            float4 v = __ldcs(&e[d * (OO / 4)]);   // evict-first: pure stream
            float xv = xs[d];
            acc.x = fmaf(xv, v.x, acc.x);
            acc.y = fmaf(xv, v.y, acc.y);
            acc.z = fmaf(xv, v.z, acc.z);
            acc.w = fmaf(xv, v.w, acc.w);
        }

        // ---- gate: wait for all GEMM CTAs (in practice already done) ----
        if (tid == 0) {
            volatile int* done = &g_done;
            while (*done < GEMM_CTAS) { }
        }
        __syncthreads();
        __threadfence();   // acquire: order the out-row read after the flag

        // out[p,:] currently holds x@W + bias + bias_eps (written by GEMM CTAs).
        float4* orow = (float4*)(out + (size_t)p * OO);
        float4 base = __ldcg(&orow[tid]);   // L2-hot (written ~130us earlier)

        float4 o;
        o.x = acc.x + base.x;
        o.y = acc.y + base.y;
        o.z = acc.z + base.z;
        o.w = acc.w + base.w;
        __stcs(&orow[tid], o);   // write-once stream

        // ---- self-reset for next graph replay ----
        if (tid == 0) {
            int old = atomicAdd(&g_stream_done, 1);
            if (old == PP - 1) {
                // All stream CTAs have passed the gate; safe to reset.
                atomicExch(&g_stream_done, 0);
                atomicExch(&g_done, 0);
            }
        }
    } else {
        // ---- GEMM CTA: 32x64 tile, writes out = x@W + bias + bias_eps ----
        __shared__ float As[16][32];   // [k][m]
        __shared__ float Bs[16][64];   // [k][n]

        const int g  = bid;
        const int bm = (g >> 3) * 32;
        const int bn = (g & 7) * 64;
        const int tx = tid & 15;
        const int ty = tid >> 4;

        float acc[4][4];
        #pragma unroll
        for (int i = 0; i < 4; i++)
            #pragma unroll
            for (int j = 0; j < 4; j++) acc[i][j] = 0.0f;

        for (int k0 = 0; k0 < DD; k0 += 16) {
            {
                const int r  = tid >> 2;           // 0..31
                const int c4 = (tid & 3) * 4;      // 0,4,8,12
                float4 a = *(const float4*)&x[(size_t)(bm + r) * DD + k0 + c4];
                As[c4 + 0][r] = a.x;
                As[c4 + 1][r] = a.y;
                As[c4 + 2][r] = a.z;
                As[c4 + 3][r] = a.w;
            }
            {
                const int r  = tid >> 4;           // 0..7
                const int c4 = (tid & 15) * 4;
                *(float4*)&Bs[r][c4]     = *(const float4*)&w[(size_t)(k0 + r) * OO + bn + c4];
                *(float4*)&Bs[r + 8][c4] = *(const float4*)&w[(size_t)(k0 + r + 8) * OO + bn + c4];
            }
            __syncthreads();

            #pragma unroll
            for (int k = 0; k < 16; k++) {
                float4 a = *(const float4*)&As[k][ty * 4];
                float4 b = *(const float4*)&Bs[k][tx * 4];
                float av[4] = {a.x, a.y, a.z, a.w};
                float bv[4] = {b.x, b.y, b.z, b.w};
                #pragma unroll
                for (int i = 0; i < 4; i++)
                    #pragma unroll
                    for (int j = 0; j < 4; j++)
                        acc[i][j] = fmaf(av[i], bv[j], acc[i][j]);
            }
            __syncthreads();
        }

        // Epilogue: out = acc + bias + bias_eps (stream CTAs add epsdot later).
        #pragma unroll
        for (int i = 0; i < 4; i++) {
            const int row = bm + ty * 4 + i;
            #pragma unroll
            for (int j = 0; j < 4; j++) {
                const int col = bn + tx * 4 + j;
                out[(size_t)row * OO + col] =
                    acc[i][j] + bias[col]
                    + __ldcs(&bias_eps[(size_t)row * OO + col]);  // read-once
            }
        }

        __threadfence();   // release: publish the out rows before the flag
        __syncthreads();
        if (tid == 0) atomicAdd(&g_done, 1);
    }
}

extern "C" void kernel_launch(void* const* d_in, const int* in_sizes, int n_in,
                              void* d_out, int out_size) {
    const float* x        = (const float*)d_in[0];
    const float* w        = (const float*)d_in[1];
    const float* bias     = (const float*)d_in[2];
    const float* eps      = (const float*)d_in[3];
    const float* bias_eps = (const float*)d_in[4];
    float*       out      = (float*)d_out;

    (void)in_sizes; (void)n_in; (void)out_size;

    nes_fused<<<PP + GEMM_CTAS, 128>>>(x, w, bias, eps, bias_eps, out);
}